// round 12
// baseline (speedup 1.0000x reference)
#include <cuda_runtime.h>
#include <cuda_bf16.h>
#include <cstdint>

#define D      256
#define MAXN   8192
#define BM     128                 // rows per row-block
#define BN     128                 // cols per tile
#define CTPB   64                  // col-tiles per row-block (MAXN/BN)
#define NTOT   4096                // total tiles = 64 rb x 64 ct
#define GRIDZ  148                 // one CTA per SM
#define SLOTS  4                   // max CTAs sharing one row-block
#define RCTAS  32                  // reduce CTAs
#define LOG2E_OVER_T 28.853900817779268f
#define INV_T        20.0f

// SMEM layout (bytes)
#define SM_PART 0                  // 2 x 128 floats
#define SM_A    2048               // 128 rows x 512 B (swizzled) = 65536
#define SM_B0   (SM_A + 65536)
#define SM_TOTAL (SM_B0 + 2 * 65536)   // 198656

// ---------------- scratch -------------------------------------------------
__device__ __align__(16) __nv_bfloat16 g_a[MAXN * D];
__device__ __align__(16) __nv_bfloat16 g_b[MAXN * D];
__device__ float g_diag[MAXN];
__device__ float g_part[MAXN * SLOTS];
__device__ float g_bsum[RCTAS];
__device__ int   g_ticket;

// ---------------- helpers --------------------------------------------------
__device__ __forceinline__ uint32_t smem_u32(const void* p) {
    return (uint32_t)__cvta_generic_to_shared(p);
}
__device__ __forceinline__ void cp_async16(uint32_t sdst, const void* gsrc) {
    asm volatile("cp.async.cg.shared.global [%0], [%1], 16;\n" :: "r"(sdst), "l"(gsrc));
}
#define CP_COMMIT() asm volatile("cp.async.commit_group;\n" ::: "memory")
#define CP_WAIT1()  asm volatile("cp.async.wait_group 1;\n" ::: "memory")

__device__ __forceinline__ float ex2f(float x) {
    float y; asm("ex2.approx.f32 %0, %1;" : "=f"(y) : "f"(x)); return y;
}
__device__ __forceinline__ void ldsm_x4(uint32_t r[4], uint32_t addr) {
    asm volatile("ldmatrix.sync.aligned.m8n8.x4.shared.b16 {%0,%1,%2,%3}, [%4];"
                 : "=r"(r[0]), "=r"(r[1]), "=r"(r[2]), "=r"(r[3]) : "r"(addr));
}
__device__ __forceinline__ void mma_bf16(float c[4], const uint32_t a[4],
                                         uint32_t b0, uint32_t b1) {
    asm volatile(
        "mma.sync.aligned.m16n8k16.row.col.f32.bf16.bf16.f32 "
        "{%0,%1,%2,%3}, {%4,%5,%6,%7}, {%8,%9}, {%0,%1,%2,%3};\n"
        : "+f"(c[0]), "+f"(c[1]), "+f"(c[2]), "+f"(c[3])
        : "r"(a[0]), "r"(a[1]), "r"(a[2]), "r"(a[3]), "r"(b0), "r"(b1));
}

// cp.async loader: 128x256 bf16 tile (64KB), XOR-swizzled 16B chunks, 256 threads
__device__ __forceinline__ void load_tile(uint32_t sdst_base,
                                          const __nv_bfloat16* gsrc, int tid) {
    int c = tid & 31, r8 = tid >> 5;
    #pragma unroll
    for (int p = 0; p < 16; p++) {
        int row = p * 8 + r8;
        uint32_t sdst = sdst_base + row * 512 + (((uint32_t)(c ^ (row & 7))) << 4);
        cp_async16(sdst, gsrc + (size_t)row * D + c * 8);
    }
}

// ---------------- kernel 1: norms + exact diagonal (2 rows/warp) -----------
__global__ void norm_kernel(const float4* __restrict__ a4, const float4* __restrict__ b4) {
    // zero the partial-sum slots + ticket (rewritten each run)
    int gt = blockIdx.x * 256 + threadIdx.x;
    if (gt < MAXN * SLOTS) g_part[gt] = 0.f;
    if (gt == 0) g_ticket = 0;

    int w = threadIdx.x >> 5, lane = threadIdx.x & 31;
    int r0 = blockIdx.x * 16 + w * 2;          // this warp: rows r0, r0+1

    const float4* ar0 = a4 + (size_t)r0 * (D / 4);
    const float4* br0 = b4 + (size_t)r0 * (D / 4);
    const float4* ar1 = ar0 + (D / 4);
    const float4* br1 = br0 + (D / 4);

    float4 xa0 = ar0[lane * 2], xa1 = ar0[lane * 2 + 1];
    float4 xb0 = br0[lane * 2], xb1 = br0[lane * 2 + 1];
    float4 ya0 = ar1[lane * 2], ya1 = ar1[lane * 2 + 1];
    float4 yb0 = br1[lane * 2], yb1 = br1[lane * 2 + 1];

    float sa0 = xa0.x*xa0.x + xa0.y*xa0.y + xa0.z*xa0.z + xa0.w*xa0.w
              + xa1.x*xa1.x + xa1.y*xa1.y + xa1.z*xa1.z + xa1.w*xa1.w;
    float sb0 = xb0.x*xb0.x + xb0.y*xb0.y + xb0.z*xb0.z + xb0.w*xb0.w
              + xb1.x*xb1.x + xb1.y*xb1.y + xb1.z*xb1.z + xb1.w*xb1.w;
    float sd0 = xa0.x*xb0.x + xa0.y*xb0.y + xa0.z*xb0.z + xa0.w*xb0.w
              + xa1.x*xb1.x + xa1.y*xb1.y + xa1.z*xb1.z + xa1.w*xb1.w;
    float sa1 = ya0.x*ya0.x + ya0.y*ya0.y + ya0.z*ya0.z + ya0.w*ya0.w
              + ya1.x*ya1.x + ya1.y*ya1.y + ya1.z*ya1.z + ya1.w*ya1.w;
    float sb1 = yb0.x*yb0.x + yb0.y*yb0.y + yb0.z*yb0.z + yb0.w*yb0.w
              + yb1.x*yb1.x + yb1.y*yb1.y + yb1.z*yb1.z + yb1.w*yb1.w;
    float sd1 = ya0.x*yb0.x + ya0.y*yb0.y + ya0.z*yb0.z + ya0.w*yb0.w
              + ya1.x*yb1.x + ya1.y*yb1.y + ya1.z*yb1.z + ya1.w*yb1.w;

    #pragma unroll
    for (int o = 16; o; o >>= 1) {
        sa0 += __shfl_xor_sync(0xffffffffu, sa0, o);
        sa1 += __shfl_xor_sync(0xffffffffu, sa1, o);
        sb0 += __shfl_xor_sync(0xffffffffu, sb0, o);
        sb1 += __shfl_xor_sync(0xffffffffu, sb1, o);
        sd0 += __shfl_xor_sync(0xffffffffu, sd0, o);
        sd1 += __shfl_xor_sync(0xffffffffu, sd1, o);
    }
    float ia0 = rsqrtf(fmaxf(sa0, 1e-16f)), ib0 = rsqrtf(fmaxf(sb0, 1e-16f));
    float ia1 = rsqrtf(fmaxf(sa1, 1e-16f)), ib1 = rsqrtf(fmaxf(sb1, 1e-16f));
    if (lane == 0) {
        g_diag[r0]     = sd0 * ia0 * ib0 * INV_T;
        g_diag[r0 + 1] = sd1 * ia1 * ib1 * INV_T;
    }

    float fa0 = ia0 * LOG2E_OVER_T, fa1 = ia1 * LOG2E_OVER_T;
    {
        __nv_bfloat162 p0 = __floats2bfloat162_rn(xa0.x*fa0, xa0.y*fa0);
        __nv_bfloat162 p1 = __floats2bfloat162_rn(xa0.z*fa0, xa0.w*fa0);
        __nv_bfloat162 p2 = __floats2bfloat162_rn(xa1.x*fa0, xa1.y*fa0);
        __nv_bfloat162 p3 = __floats2bfloat162_rn(xa1.z*fa0, xa1.w*fa0);
        uint4 u = { *(uint32_t*)&p0, *(uint32_t*)&p1, *(uint32_t*)&p2, *(uint32_t*)&p3 };
        *(uint4*)(g_a + (size_t)r0 * D + lane * 8) = u;
    }
    {
        __nv_bfloat162 p0 = __floats2bfloat162_rn(ya0.x*fa1, ya0.y*fa1);
        __nv_bfloat162 p1 = __floats2bfloat162_rn(ya0.z*fa1, ya0.w*fa1);
        __nv_bfloat162 p2 = __floats2bfloat162_rn(ya1.x*fa1, ya1.y*fa1);
        __nv_bfloat162 p3 = __floats2bfloat162_rn(ya1.z*fa1, ya1.w*fa1);
        uint4 u = { *(uint32_t*)&p0, *(uint32_t*)&p1, *(uint32_t*)&p2, *(uint32_t*)&p3 };
        *(uint4*)(g_a + (size_t)(r0 + 1) * D + lane * 8) = u;
    }
    {
        __nv_bfloat162 q0 = __floats2bfloat162_rn(xb0.x*ib0, xb0.y*ib0);
        __nv_bfloat162 q1 = __floats2bfloat162_rn(xb0.z*ib0, xb0.w*ib0);
        __nv_bfloat162 q2 = __floats2bfloat162_rn(xb1.x*ib0, xb1.y*ib0);
        __nv_bfloat162 q3 = __floats2bfloat162_rn(xb1.z*ib0, xb1.w*ib0);
        uint4 u = { *(uint32_t*)&q0, *(uint32_t*)&q1, *(uint32_t*)&q2, *(uint32_t*)&q3 };
        *(uint4*)(g_b + (size_t)r0 * D + lane * 8) = u;
    }
    {
        __nv_bfloat162 q0 = __floats2bfloat162_rn(yb0.x*ib1, yb0.y*ib1);
        __nv_bfloat162 q1 = __floats2bfloat162_rn(yb0.z*ib1, yb0.w*ib1);
        __nv_bfloat162 q2 = __floats2bfloat162_rn(yb1.x*ib1, yb1.y*ib1);
        __nv_bfloat162 q3 = __floats2bfloat162_rn(yb1.z*ib1, yb1.w*ib1);
        uint4 u = { *(uint32_t*)&q0, *(uint32_t*)&q1, *(uint32_t*)&q2, *(uint32_t*)&q3 };
        *(uint4*)(g_b + (size_t)(r0 + 1) * D + lane * 8) = u;
    }
}

// ---------------- kernel 2: balanced-partition HMMA GEMM + ex2 (R9) --------
__global__ __launch_bounds__(256, 1) void sim_lse_kernel() {
    extern __shared__ char sm[];
    uint32_t sbase = smem_u32(sm);
    int tid = threadIdx.x, w = tid >> 5, lane = tid & 31;
    int cta = blockIdx.x;
    int gStart = (cta * NTOT) / GRIDZ;
    int gEnd   = ((cta + 1) * NTOT) / GRIDZ;

    int wr = (w & 3) * 32;        // warp row offset
    int wc = (w >> 2) * 64;       // warp col offset
    int g2 = lane >> 3, l3 = lane & 7;
    uint32_t rk = (uint32_t)(l3 >> 1);

    uint32_t abase[2], boff[4];
    {
        uint32_t c0a = (uint32_t)(((g2 >> 1) ^ (l3 & 1)) << 4);
        uint32_t c0b = (uint32_t)(((g2 & 1) ^ (l3 & 1)) << 4);
        #pragma unroll
        for (int mt = 0; mt < 2; mt++) {
            int row = wr + mt * 16 + (g2 & 1) * 8 + l3;
            abase[mt] = sbase + SM_A + row * 512 + c0a;
        }
        #pragma unroll
        for (int nt = 0; nt < 4; nt++) {
            int n = wc + nt * 16 + (g2 >> 1) * 8 + l3;
            boff[nt] = (uint32_t)(n * 512) + c0b;
        }
    }

    int rb = gStart >> 6;
    load_tile(sbase + SM_A, g_a + (size_t)rb * BM * D, tid);
    load_tile(sbase + SM_B0 + (gStart & 1) * 65536,
              g_b + (size_t)(gStart & (CTPB - 1)) * BN * D, tid);
    CP_COMMIT();

    float acc[2][8][4];
    #pragma unroll
    for (int mt = 0; mt < 2; mt++)
        #pragma unroll
        for (int j = 0; j < 8; j++)
            acc[mt][j][0] = acc[mt][j][1] = acc[mt][j][2] = acc[mt][j][3] = 0.f;
    float rs0[2] = {0, 0}, rs1[2] = {0, 0};
    float* partial = (float*)(sm + SM_PART);

    for (int g = gStart; g < gEnd; g++) {
        __syncthreads();
        if (g + 1 < gEnd)
            load_tile(sbase + SM_B0 + ((g + 1) & 1) * 65536,
                      g_b + (size_t)((g + 1) & (CTPB - 1)) * BN * D, tid);
        CP_COMMIT();
        CP_WAIT1();
        __syncthreads();

        uint32_t bbuf = sbase + SM_B0 + (g & 1) * 65536;

        #pragma unroll
        for (int kk = 0; kk < 16; kk++) {
            uint32_t koff = ((uint32_t)(kk ^ rk)) << 5;
            uint32_t af[2][4], bf[4][4];
            #pragma unroll
            for (int mt = 0; mt < 2; mt++) ldsm_x4(af[mt], abase[mt] + koff);
            #pragma unroll
            for (int nt = 0; nt < 4; nt++) ldsm_x4(bf[nt], bbuf + boff[nt] + koff);
            #pragma unroll
            for (int mt = 0; mt < 2; mt++) {
                #pragma unroll
                for (int nt = 0; nt < 4; nt++) {
                    mma_bf16(acc[mt][nt * 2],     af[mt], bf[nt][0], bf[nt][1]);
                    mma_bf16(acc[mt][nt * 2 + 1], af[mt], bf[nt][2], bf[nt][3]);
                }
            }
        }
        #pragma unroll
        for (int mt = 0; mt < 2; mt++)
            #pragma unroll
            for (int j = 0; j < 8; j++) {
                rs0[mt] += ex2f(acc[mt][j][0]) + ex2f(acc[mt][j][1]);
                rs1[mt] += ex2f(acc[mt][j][2]) + ex2f(acc[mt][j][3]);
                acc[mt][j][0] = acc[mt][j][1] = acc[mt][j][2] = acc[mt][j][3] = 0.f;
            }

        if ((((g + 1) & (CTPB - 1)) == 0) || (g + 1 == gEnd)) {
            #pragma unroll
            for (int mt = 0; mt < 2; mt++) {
                rs0[mt] += __shfl_xor_sync(0xffffffffu, rs0[mt], 1);
                rs0[mt] += __shfl_xor_sync(0xffffffffu, rs0[mt], 2);
                rs1[mt] += __shfl_xor_sync(0xffffffffu, rs1[mt], 1);
                rs1[mt] += __shfl_xor_sync(0xffffffffu, rs1[mt], 2);
            }
            if ((lane & 3) == 0) {
                int half = (w >> 2) * 128;
                #pragma unroll
                for (int mt = 0; mt < 2; mt++) {
                    partial[half + wr + mt * 16 + (lane >> 2)]     = rs0[mt];
                    partial[half + wr + mt * 16 + 8 + (lane >> 2)] = rs1[mt];
                }
            }
            __syncthreads();
            int ft = rb << 6;
            int i0 = (ft * GRIDZ) / NTOT;
            while (((i0 + 1) * NTOT) / GRIDZ <= ft) i0++;
            int slot = cta - i0;   // 0..SLOTS-1
            if (tid < 128)
                g_part[(size_t)(rb * BM + tid) * SLOTS + slot] =
                    partial[tid] + partial[128 + tid];
            rs0[0] = rs0[1] = rs1[0] = rs1[1] = 0.f;
            if (g + 1 < gEnd && (((g + 1) & (CTPB - 1)) == 0)) {
                rb = (g + 1) >> 6;
                load_tile(sbase + SM_A, g_a + (size_t)rb * BM * D, tid);
                CP_COMMIT();
            }
        }
    }
}

// ---------------- kernel 3: per-row LSE terms + fused final sum ------------
__global__ void reduce_rows_kernel(float* __restrict__ out, int N) {
    __shared__ float s[8];
    __shared__ int lastFlag;
    int t = threadIdx.x;
    int row = blockIdx.x * 256 + t;            // RCTAS*256 = 8192 rows
    const float* p = g_part + (size_t)row * SLOTS;
    float sum2 = (p[0] + p[1]) + (p[2] + p[3]);
    float v = __logf(sum2) - g_diag[row];      // LSE - diag (natural units)
    #pragma unroll
    for (int o = 16; o; o >>= 1) v += __shfl_xor_sync(0xffffffffu, v, o);
    if ((t & 31) == 0) s[t >> 5] = v;
    __syncthreads();
    if (t == 0) {
        float x = 0.f;
        #pragma unroll
        for (int i = 0; i < 8; i++) x += s[i];
        g_bsum[blockIdx.x] = x;
        __threadfence();
        int old = atomicAdd(&g_ticket, 1);
        lastFlag = (old == RCTAS - 1);
    }
    __syncthreads();
    if (lastFlag && t < 32) {                  // last CTA does the final sum
        __threadfence();                       // acquire: g_bsum writes visible
        float x = (t < RCTAS) ? g_bsum[t] : 0.f;
        #pragma unroll
        for (int o = 16; o; o >>= 1) x += __shfl_xor_sync(0xffffffffu, x, o);
        if (t == 0) out[0] = x / (float)N;
    }
}

// ---------------- launch ---------------------------------------------------
extern "C" void kernel_launch(void* const* d_in, const int* in_sizes, int n_in,
                              void* d_out, int out_size) {
    const float* a = (const float*)d_in[0];
    const float* b = (const float*)d_in[1];
    int N = in_sizes[0] / D;   // 8192

    cudaFuncSetAttribute(sim_lse_kernel,
                         cudaFuncAttributeMaxDynamicSharedMemorySize, SM_TOTAL);

    norm_kernel<<<N / 16, 256>>>((const float4*)a, (const float4*)b);
    sim_lse_kernel<<<GRIDZ, 256, SM_TOTAL>>>();
    reduce_rows_kernel<<<RCTAS, 256>>>((float*)d_out, N);
}

// round 13
// speedup vs baseline: 1.0173x; 1.0173x over previous
#include <cuda_runtime.h>
#include <cuda_bf16.h>
#include <cstdint>

#define D      256
#define MAXN   8192
#define BM     128                 // rows per row-block
#define BN     128                 // cols per tile
#define CTPB   64                  // col-tiles per row-block (MAXN/BN)
#define NTOT   4096                // total tiles = 64 rb x 64 ct
#define GRIDZ  148                 // one CTA per SM
#define SLOTS  4                   // max CTAs sharing one row-block
#define RCTAS  32                  // reduce stage-A CTAs
#define LOG2E_OVER_T 28.853900817779268f
#define INV_T        20.0f

// SMEM layout (bytes)
#define SM_PART 0                  // 2 x 128 floats
#define SM_A    2048               // 128 rows x 512 B (swizzled) = 65536
#define SM_B0   (SM_A + 65536)
#define SM_TOTAL (SM_B0 + 2 * 65536)   // 198656

// ---------------- scratch -------------------------------------------------
__device__ __align__(16) __nv_bfloat16 g_a[MAXN * D];
__device__ __align__(16) __nv_bfloat16 g_b[MAXN * D];
__device__ float g_diag[MAXN];
__device__ float g_part[MAXN * SLOTS];
__device__ float g_bsum[RCTAS];

// ---------------- helpers --------------------------------------------------
__device__ __forceinline__ uint32_t smem_u32(const void* p) {
    return (uint32_t)__cvta_generic_to_shared(p);
}
__device__ __forceinline__ void cp_async16(uint32_t sdst, const void* gsrc) {
    asm volatile("cp.async.cg.shared.global [%0], [%1], 16;\n" :: "r"(sdst), "l"(gsrc));
}
#define CP_COMMIT() asm volatile("cp.async.commit_group;\n" ::: "memory")
#define CP_WAIT1()  asm volatile("cp.async.wait_group 1;\n" ::: "memory")

__device__ __forceinline__ float ex2f(float x) {
    float y; asm("ex2.approx.f32 %0, %1;" : "=f"(y) : "f"(x)); return y;
}
__device__ __forceinline__ void ldsm_x4(uint32_t r[4], uint32_t addr) {
    asm volatile("ldmatrix.sync.aligned.m8n8.x4.shared.b16 {%0,%1,%2,%3}, [%4];"
                 : "=r"(r[0]), "=r"(r[1]), "=r"(r[2]), "=r"(r[3]) : "r"(addr));
}
__device__ __forceinline__ void mma_bf16(float c[4], const uint32_t a[4],
                                         uint32_t b0, uint32_t b1) {
    asm volatile(
        "mma.sync.aligned.m16n8k16.row.col.f32.bf16.bf16.f32 "
        "{%0,%1,%2,%3}, {%4,%5,%6,%7}, {%8,%9}, {%0,%1,%2,%3};\n"
        : "+f"(c[0]), "+f"(c[1]), "+f"(c[2]), "+f"(c[3])
        : "r"(a[0]), "r"(a[1]), "r"(a[2]), "r"(a[3]), "r"(b0), "r"(b1));
}

// cp.async loader: 128x256 bf16 tile (64KB), XOR-swizzled 16B chunks, 256 threads
__device__ __forceinline__ void load_tile(uint32_t sdst_base,
                                          const __nv_bfloat16* gsrc, int tid) {
    int c = tid & 31, r8 = tid >> 5;
    #pragma unroll
    for (int p = 0; p < 16; p++) {
        int row = p * 8 + r8;
        uint32_t sdst = sdst_base + row * 512 + (((uint32_t)(c ^ (row & 7))) << 4);
        cp_async16(sdst, gsrc + (size_t)row * D + c * 8);
    }
}

// ---------------- kernel 1: norms + exact diagonal (R10: 1 row/warp) -------
__global__ void norm_kernel(const float4* __restrict__ a4, const float4* __restrict__ b4) {
    // zero the partial-sum slots (grid 1024 x 256 covers 32768 floats)
    int gt = blockIdx.x * 256 + threadIdx.x;
    if (gt < MAXN * SLOTS) g_part[gt] = 0.f;

    int w = threadIdx.x >> 5, lane = threadIdx.x & 31;
    int row = blockIdx.x * 8 + w;
    const float4* ar = a4 + (size_t)row * (D / 4);
    const float4* br = b4 + (size_t)row * (D / 4);
    float4 a0 = ar[lane * 2], a1 = ar[lane * 2 + 1];
    float4 b0 = br[lane * 2], b1 = br[lane * 2 + 1];

    float sa = a0.x*a0.x + a0.y*a0.y + a0.z*a0.z + a0.w*a0.w
             + a1.x*a1.x + a1.y*a1.y + a1.z*a1.z + a1.w*a1.w;
    float sb = b0.x*b0.x + b0.y*b0.y + b0.z*b0.z + b0.w*b0.w
             + b1.x*b1.x + b1.y*b1.y + b1.z*b1.z + b1.w*b1.w;
    float sd = a0.x*b0.x + a0.y*b0.y + a0.z*b0.z + a0.w*b0.w
             + a1.x*b1.x + a1.y*b1.y + a1.z*b1.z + a1.w*b1.w;
    #pragma unroll
    for (int o = 16; o; o >>= 1) {
        sa += __shfl_xor_sync(0xffffffffu, sa, o);
        sb += __shfl_xor_sync(0xffffffffu, sb, o);
        sd += __shfl_xor_sync(0xffffffffu, sd, o);
    }
    float ia = rsqrtf(fmaxf(sa, 1e-16f));
    float ib = rsqrtf(fmaxf(sb, 1e-16f));
    if (lane == 0) g_diag[row] = sd * ia * ib * INV_T;

    float fa = ia * LOG2E_OVER_T;
    __nv_bfloat162 p0 = __floats2bfloat162_rn(a0.x*fa, a0.y*fa);
    __nv_bfloat162 p1 = __floats2bfloat162_rn(a0.z*fa, a0.w*fa);
    __nv_bfloat162 p2 = __floats2bfloat162_rn(a1.x*fa, a1.y*fa);
    __nv_bfloat162 p3 = __floats2bfloat162_rn(a1.z*fa, a1.w*fa);
    uint4 ua = { *(uint32_t*)&p0, *(uint32_t*)&p1, *(uint32_t*)&p2, *(uint32_t*)&p3 };
    *(uint4*)(g_a + (size_t)row * D + lane * 8) = ua;

    __nv_bfloat162 q0 = __floats2bfloat162_rn(b0.x*ib, b0.y*ib);
    __nv_bfloat162 q1 = __floats2bfloat162_rn(b0.z*ib, b0.w*ib);
    __nv_bfloat162 q2 = __floats2bfloat162_rn(b1.x*ib, b1.y*ib);
    __nv_bfloat162 q3 = __floats2bfloat162_rn(b1.z*ib, b1.w*ib);
    uint4 ub = { *(uint32_t*)&q0, *(uint32_t*)&q1, *(uint32_t*)&q2, *(uint32_t*)&q3 };
    *(uint4*)(g_b + (size_t)row * D + lane * 8) = ub;
}

// ---------------- kernel 2: balanced-partition HMMA GEMM + ex2 (R9/R11) ----
__global__ __launch_bounds__(256, 1) void sim_lse_kernel() {
    extern __shared__ char sm[];
    uint32_t sbase = smem_u32(sm);
    int tid = threadIdx.x, w = tid >> 5, lane = tid & 31;
    int cta = blockIdx.x;
    int gStart = (cta * NTOT) / GRIDZ;
    int gEnd   = ((cta + 1) * NTOT) / GRIDZ;

    int wr = (w & 3) * 32;        // warp row offset
    int wc = (w >> 2) * 64;       // warp col offset
    int g2 = lane >> 3, l3 = lane & 7;
    uint32_t rk = (uint32_t)(l3 >> 1);

    uint32_t abase[2], boff[4];
    {
        uint32_t c0a = (uint32_t)(((g2 >> 1) ^ (l3 & 1)) << 4);
        uint32_t c0b = (uint32_t)(((g2 & 1) ^ (l3 & 1)) << 4);
        #pragma unroll
        for (int mt = 0; mt < 2; mt++) {
            int row = wr + mt * 16 + (g2 & 1) * 8 + l3;
            abase[mt] = sbase + SM_A + row * 512 + c0a;
        }
        #pragma unroll
        for (int nt = 0; nt < 4; nt++) {
            int n = wc + nt * 16 + (g2 >> 1) * 8 + l3;
            boff[nt] = (uint32_t)(n * 512) + c0b;
        }
    }

    int rb = gStart >> 6;
    load_tile(sbase + SM_A, g_a + (size_t)rb * BM * D, tid);
    load_tile(sbase + SM_B0 + (gStart & 1) * 65536,
              g_b + (size_t)(gStart & (CTPB - 1)) * BN * D, tid);
    CP_COMMIT();

    float acc[2][8][4];
    #pragma unroll
    for (int mt = 0; mt < 2; mt++)
        #pragma unroll
        for (int j = 0; j < 8; j++)
            acc[mt][j][0] = acc[mt][j][1] = acc[mt][j][2] = acc[mt][j][3] = 0.f;
    float rs0[2] = {0, 0}, rs1[2] = {0, 0};
    float* partial = (float*)(sm + SM_PART);

    for (int g = gStart; g < gEnd; g++) {
        __syncthreads();
        if (g + 1 < gEnd)
            load_tile(sbase + SM_B0 + ((g + 1) & 1) * 65536,
                      g_b + (size_t)((g + 1) & (CTPB - 1)) * BN * D, tid);
        CP_COMMIT();
        CP_WAIT1();
        __syncthreads();

        uint32_t bbuf = sbase + SM_B0 + (g & 1) * 65536;

        #pragma unroll
        for (int kk = 0; kk < 16; kk++) {
            uint32_t koff = ((uint32_t)(kk ^ rk)) << 5;
            uint32_t af[2][4], bf[4][4];
            #pragma unroll
            for (int mt = 0; mt < 2; mt++) ldsm_x4(af[mt], abase[mt] + koff);
            #pragma unroll
            for (int nt = 0; nt < 4; nt++) ldsm_x4(bf[nt], bbuf + boff[nt] + koff);
            #pragma unroll
            for (int mt = 0; mt < 2; mt++) {
                #pragma unroll
                for (int nt = 0; nt < 4; nt++) {
                    mma_bf16(acc[mt][nt * 2],     af[mt], bf[nt][0], bf[nt][1]);
                    mma_bf16(acc[mt][nt * 2 + 1], af[mt], bf[nt][2], bf[nt][3]);
                }
            }
        }
        #pragma unroll
        for (int mt = 0; mt < 2; mt++)
            #pragma unroll
            for (int j = 0; j < 8; j++) {
                rs0[mt] += ex2f(acc[mt][j][0]) + ex2f(acc[mt][j][1]);
                rs1[mt] += ex2f(acc[mt][j][2]) + ex2f(acc[mt][j][3]);
                acc[mt][j][0] = acc[mt][j][1] = acc[mt][j][2] = acc[mt][j][3] = 0.f;
            }

        if ((((g + 1) & (CTPB - 1)) == 0) || (g + 1 == gEnd)) {
            #pragma unroll
            for (int mt = 0; mt < 2; mt++) {
                rs0[mt] += __shfl_xor_sync(0xffffffffu, rs0[mt], 1);
                rs0[mt] += __shfl_xor_sync(0xffffffffu, rs0[mt], 2);
                rs1[mt] += __shfl_xor_sync(0xffffffffu, rs1[mt], 1);
                rs1[mt] += __shfl_xor_sync(0xffffffffu, rs1[mt], 2);
            }
            if ((lane & 3) == 0) {
                int half = (w >> 2) * 128;
                #pragma unroll
                for (int mt = 0; mt < 2; mt++) {
                    partial[half + wr + mt * 16 + (lane >> 2)]     = rs0[mt];
                    partial[half + wr + mt * 16 + 8 + (lane >> 2)] = rs1[mt];
                }
            }
            __syncthreads();
            int ft = rb << 6;
            int i0 = (ft * GRIDZ) / NTOT;
            while (((i0 + 1) * NTOT) / GRIDZ <= ft) i0++;
            int slot = cta - i0;   // 0..SLOTS-1
            if (tid < 128)
                g_part[(size_t)(rb * BM + tid) * SLOTS + slot] =
                    partial[tid] + partial[128 + tid];
            rs0[0] = rs0[1] = rs1[0] = rs1[1] = 0.f;
            if (g + 1 < gEnd && (((g + 1) & (CTPB - 1)) == 0)) {
                rb = (g + 1) >> 6;
                load_tile(sbase + SM_A, g_a + (size_t)rb * BM * D, tid);
                CP_COMMIT();
            }
        }
    }
}

// ---------------- kernel 3a: per-row LSE terms, 32 CTAs --------------------
__global__ void reduce_rows_kernel() {
    __shared__ float s[8];
    int t = threadIdx.x;
    int row = blockIdx.x * 256 + t;            // RCTAS*256 = 8192 rows
    const float* p = g_part + (size_t)row * SLOTS;
    float sum2 = (p[0] + p[1]) + (p[2] + p[3]);
    float v = __logf(sum2) - g_diag[row];      // LSE - diag (natural units)
    #pragma unroll
    for (int o = 16; o; o >>= 1) v += __shfl_xor_sync(0xffffffffu, v, o);
    if ((t & 31) == 0) s[t >> 5] = v;
    __syncthreads();
    if (t < 32) {
        float x = (t < 8) ? s[t] : 0.f;
        #pragma unroll
        for (int o = 4; o; o >>= 1) x += __shfl_xor_sync(0xffffffffu, x, o);
        if (t == 0) g_bsum[blockIdx.x] = x;
    }
}

// ---------------- kernel 3b: final sum ------------------------------------
__global__ void reduce_final_kernel(float* __restrict__ out, int N) {
    int t = threadIdx.x;
    float x = (t < RCTAS) ? g_bsum[t] : 0.f;
    #pragma unroll
    for (int o = 16; o; o >>= 1) x += __shfl_xor_sync(0xffffffffu, x, o);
    if (t == 0) out[0] = x / (float)N;
}

// ---------------- launch ---------------------------------------------------
extern "C" void kernel_launch(void* const* d_in, const int* in_sizes, int n_in,
                              void* d_out, int out_size) {
    const float* a = (const float*)d_in[0];
    const float* b = (const float*)d_in[1];
    int N = in_sizes[0] / D;   // 8192

    cudaFuncSetAttribute(sim_lse_kernel,
                         cudaFuncAttributeMaxDynamicSharedMemorySize, SM_TOTAL);

    norm_kernel<<<N / 8, 256>>>((const float4*)a, (const float4*)b);
    sim_lse_kernel<<<GRIDZ, 256, SM_TOTAL>>>();
    reduce_rows_kernel<<<RCTAS, 256>>>();
    reduce_final_kernel<<<1, 32>>>((float*)d_out, N);
}

// round 14
// speedup vs baseline: 1.0353x; 1.0177x over previous
#include <cuda_runtime.h>
#include <cuda_bf16.h>
#include <cstdint>

#define D      256
#define MAXN   8192
#define BM     128                 // rows per row-block
#define BN     128                 // cols per tile
#define CTPB   64                  // col-tiles per row-block (MAXN/BN)
#define NTOT   4096                // total tiles = 64 rb x 64 ct
#define GRIDZ  148                 // one CTA per SM
#define SLOTS  4                   // max CTAs sharing one row-block
#define RCTAS  32                  // reduce stage-A CTAs
#define LOG2E_OVER_T 28.853900817779268f
#define INV_T        20.0f

// SMEM layout (bytes)
#define SM_PART 0                  // 2 x 128 floats
#define SM_A    2048               // 128 rows x 512 B (swizzled) = 65536
#define SM_B0   (SM_A + 65536)
#define SM_TOTAL (SM_B0 + 2 * 65536)   // 198656

// ---------------- scratch -------------------------------------------------
__device__ __align__(16) __nv_bfloat16 g_a[MAXN * D];
__device__ __align__(16) __nv_bfloat16 g_b[MAXN * D];
__device__ float g_diag[MAXN];
__device__ float g_part[MAXN * SLOTS];
__device__ float g_bsum[RCTAS];

// ---------------- helpers --------------------------------------------------
__device__ __forceinline__ uint32_t smem_u32(const void* p) {
    return (uint32_t)__cvta_generic_to_shared(p);
}
__device__ __forceinline__ void cp_async16(uint32_t sdst, const void* gsrc) {
    asm volatile("cp.async.cg.shared.global [%0], [%1], 16;\n" :: "r"(sdst), "l"(gsrc));
}
#define CP_COMMIT() asm volatile("cp.async.commit_group;\n" ::: "memory")
#define CP_WAIT0()  asm volatile("cp.async.wait_group 0;\n" ::: "memory")

__device__ __forceinline__ float ex2f(float x) {
    float y; asm("ex2.approx.f32 %0, %1;" : "=f"(y) : "f"(x)); return y;
}
__device__ __forceinline__ void ldsm_x4(uint32_t r[4], uint32_t addr) {
    asm volatile("ldmatrix.sync.aligned.m8n8.x4.shared.b16 {%0,%1,%2,%3}, [%4];"
                 : "=r"(r[0]), "=r"(r[1]), "=r"(r[2]), "=r"(r[3]) : "r"(addr));
}
__device__ __forceinline__ void mma_bf16(float c[4], const uint32_t a[4],
                                         uint32_t b0, uint32_t b1) {
    asm volatile(
        "mma.sync.aligned.m16n8k16.row.col.f32.bf16.bf16.f32 "
        "{%0,%1,%2,%3}, {%4,%5,%6,%7}, {%8,%9}, {%0,%1,%2,%3};\n"
        : "+f"(c[0]), "+f"(c[1]), "+f"(c[2]), "+f"(c[3])
        : "r"(a[0]), "r"(a[1]), "r"(a[2]), "r"(a[3]), "r"(b0), "r"(b1));
}

// cp.async loader: 128x256 bf16 tile (64KB), XOR-swizzled 16B chunks, 256 threads
__device__ __forceinline__ void load_tile(uint32_t sdst_base,
                                          const __nv_bfloat16* gsrc, int tid) {
    int c = tid & 31, r8 = tid >> 5;
    #pragma unroll
    for (int p = 0; p < 16; p++) {
        int row = p * 8 + r8;
        uint32_t sdst = sdst_base + row * 512 + (((uint32_t)(c ^ (row & 7))) << 4);
        cp_async16(sdst, gsrc + (size_t)row * D + c * 8);
    }
}

// ---------------- kernel 1: norms + exact diagonal (R10: 1 row/warp) -------
__global__ void norm_kernel(const float4* __restrict__ a4, const float4* __restrict__ b4) {
    // zero the partial-sum slots (grid 1024 x 256 covers 32768 floats)
    int gt = blockIdx.x * 256 + threadIdx.x;
    if (gt < MAXN * SLOTS) g_part[gt] = 0.f;

    int w = threadIdx.x >> 5, lane = threadIdx.x & 31;
    int row = blockIdx.x * 8 + w;
    const float4* ar = a4 + (size_t)row * (D / 4);
    const float4* br = b4 + (size_t)row * (D / 4);
    float4 a0 = ar[lane * 2], a1 = ar[lane * 2 + 1];
    float4 b0 = br[lane * 2], b1 = br[lane * 2 + 1];

    float sa = a0.x*a0.x + a0.y*a0.y + a0.z*a0.z + a0.w*a0.w
             + a1.x*a1.x + a1.y*a1.y + a1.z*a1.z + a1.w*a1.w;
    float sb = b0.x*b0.x + b0.y*b0.y + b0.z*b0.z + b0.w*b0.w
             + b1.x*b1.x + b1.y*b1.y + b1.z*b1.z + b1.w*b1.w;
    float sd = a0.x*b0.x + a0.y*b0.y + a0.z*b0.z + a0.w*b0.w
             + a1.x*b1.x + a1.y*b1.y + a1.z*b1.z + a1.w*b1.w;
    #pragma unroll
    for (int o = 16; o; o >>= 1) {
        sa += __shfl_xor_sync(0xffffffffu, sa, o);
        sb += __shfl_xor_sync(0xffffffffu, sb, o);
        sd += __shfl_xor_sync(0xffffffffu, sd, o);
    }
    float ia = rsqrtf(fmaxf(sa, 1e-16f));
    float ib = rsqrtf(fmaxf(sb, 1e-16f));
    if (lane == 0) g_diag[row] = sd * ia * ib * INV_T;

    float fa = ia * LOG2E_OVER_T;
    __nv_bfloat162 p0 = __floats2bfloat162_rn(a0.x*fa, a0.y*fa);
    __nv_bfloat162 p1 = __floats2bfloat162_rn(a0.z*fa, a0.w*fa);
    __nv_bfloat162 p2 = __floats2bfloat162_rn(a1.x*fa, a1.y*fa);
    __nv_bfloat162 p3 = __floats2bfloat162_rn(a1.z*fa, a1.w*fa);
    uint4 ua = { *(uint32_t*)&p0, *(uint32_t*)&p1, *(uint32_t*)&p2, *(uint32_t*)&p3 };
    *(uint4*)(g_a + (size_t)row * D + lane * 8) = ua;

    __nv_bfloat162 q0 = __floats2bfloat162_rn(b0.x*ib, b0.y*ib);
    __nv_bfloat162 q1 = __floats2bfloat162_rn(b0.z*ib, b0.w*ib);
    __nv_bfloat162 q2 = __floats2bfloat162_rn(b1.x*ib, b1.y*ib);
    __nv_bfloat162 q3 = __floats2bfloat162_rn(b1.z*ib, b1.w*ib);
    uint4 ub = { *(uint32_t*)&q0, *(uint32_t*)&q1, *(uint32_t*)&q2, *(uint32_t*)&q3 };
    *(uint4*)(g_b + (size_t)row * D + lane * 8) = ub;
}

// ---------------- kernel 2: balanced-partition HMMA GEMM + ex2 -------------
// Single-sync cp.async pipeline: wait_group 0 -> sync -> prefetch(g+1) -> MMA(g).
__global__ __launch_bounds__(256, 1) void sim_lse_kernel() {
    extern __shared__ char sm[];
    uint32_t sbase = smem_u32(sm);
    int tid = threadIdx.x, w = tid >> 5, lane = tid & 31;
    int cta = blockIdx.x;
    int gStart = (cta * NTOT) / GRIDZ;
    int gEnd   = ((cta + 1) * NTOT) / GRIDZ;

    int wr = (w & 3) * 32;        // warp row offset
    int wc = (w >> 2) * 64;       // warp col offset
    int g2 = lane >> 3, l3 = lane & 7;
    uint32_t rk = (uint32_t)(l3 >> 1);

    uint32_t abase[2], boff[4];
    {
        uint32_t c0a = (uint32_t)(((g2 >> 1) ^ (l3 & 1)) << 4);
        uint32_t c0b = (uint32_t)(((g2 & 1) ^ (l3 & 1)) << 4);
        #pragma unroll
        for (int mt = 0; mt < 2; mt++) {
            int row = wr + mt * 16 + (g2 & 1) * 8 + l3;
            abase[mt] = sbase + SM_A + row * 512 + c0a;
        }
        #pragma unroll
        for (int nt = 0; nt < 4; nt++) {
            int n = wc + nt * 16 + (g2 >> 1) * 8 + l3;
            boff[nt] = (uint32_t)(n * 512) + c0b;
        }
    }

    int rb = gStart >> 6;
    load_tile(sbase + SM_A, g_a + (size_t)rb * BM * D, tid);
    load_tile(sbase + SM_B0 + (gStart & 1) * 65536,
              g_b + (size_t)(gStart & (CTPB - 1)) * BN * D, tid);
    CP_COMMIT();

    float acc[2][8][4];
    #pragma unroll
    for (int mt = 0; mt < 2; mt++)
        #pragma unroll
        for (int j = 0; j < 8; j++)
            acc[mt][j][0] = acc[mt][j][1] = acc[mt][j][2] = acc[mt][j][3] = 0.f;
    float rs0[2] = {0, 0}, rs1[2] = {0, 0};
    float* partial = (float*)(sm + SM_PART);

    for (int g = gStart; g < gEnd; g++) {
        CP_WAIT0();                // tile g (and any pending A reload) arrived
        __syncthreads();           // cp.async data visible; all warps done with
                                   // iter g-1's k-loop -> buf (g+1)&1 reusable
        if (g + 1 < gEnd) {        // prefetch overlaps this tile's MMA work
            load_tile(sbase + SM_B0 + ((g + 1) & 1) * 65536,
                      g_b + (size_t)((g + 1) & (CTPB - 1)) * BN * D, tid);
            CP_COMMIT();
        }

        uint32_t bbuf = sbase + SM_B0 + (g & 1) * 65536;

        #pragma unroll
        for (int kk = 0; kk < 16; kk++) {
            uint32_t koff = ((uint32_t)(kk ^ rk)) << 5;
            uint32_t af[2][4], bf[4][4];
            #pragma unroll
            for (int mt = 0; mt < 2; mt++) ldsm_x4(af[mt], abase[mt] + koff);
            #pragma unroll
            for (int nt = 0; nt < 4; nt++) ldsm_x4(bf[nt], bbuf + boff[nt] + koff);
            #pragma unroll
            for (int mt = 0; mt < 2; mt++) {
                #pragma unroll
                for (int nt = 0; nt < 4; nt++) {
                    mma_bf16(acc[mt][nt * 2],     af[mt], bf[nt][0], bf[nt][1]);
                    mma_bf16(acc[mt][nt * 2 + 1], af[mt], bf[nt][2], bf[nt][3]);
                }
            }
        }
        #pragma unroll
        for (int mt = 0; mt < 2; mt++)
            #pragma unroll
            for (int j = 0; j < 8; j++) {
                rs0[mt] += ex2f(acc[mt][j][0]) + ex2f(acc[mt][j][1]);
                rs1[mt] += ex2f(acc[mt][j][2]) + ex2f(acc[mt][j][3]);
                acc[mt][j][0] = acc[mt][j][1] = acc[mt][j][2] = acc[mt][j][3] = 0.f;
            }

        if ((((g + 1) & (CTPB - 1)) == 0) || (g + 1 == gEnd)) {
            #pragma unroll
            for (int mt = 0; mt < 2; mt++) {
                rs0[mt] += __shfl_xor_sync(0xffffffffu, rs0[mt], 1);
                rs0[mt] += __shfl_xor_sync(0xffffffffu, rs0[mt], 2);
                rs1[mt] += __shfl_xor_sync(0xffffffffu, rs1[mt], 1);
                rs1[mt] += __shfl_xor_sync(0xffffffffu, rs1[mt], 2);
            }
            if ((lane & 3) == 0) {
                int half = (w >> 2) * 128;
                #pragma unroll
                for (int mt = 0; mt < 2; mt++) {
                    partial[half + wr + mt * 16 + (lane >> 2)]     = rs0[mt];
                    partial[half + wr + mt * 16 + 8 + (lane >> 2)] = rs1[mt];
                }
            }
            __syncthreads();       // partials visible; all warps out of k-loop
            int ft = rb << 6;
            int i0 = (ft * GRIDZ) / NTOT;
            while (((i0 + 1) * NTOT) / GRIDZ <= ft) i0++;
            int slot = cta - i0;   // 0..SLOTS-1
            if (tid < 128)
                g_part[(size_t)(rb * BM + tid) * SLOTS + slot] =
                    partial[tid] + partial[128 + tid];
            rs0[0] = rs0[1] = rs1[0] = rs1[1] = 0.f;
            if (g + 1 < gEnd && (((g + 1) & (CTPB - 1)) == 0)) {
                // safe: post-sync, no warp is still reading the old A tile
                rb = (g + 1) >> 6;
                load_tile(sbase + SM_A, g_a + (size_t)rb * BM * D, tid);
                CP_COMMIT();       // next iteration's CP_WAIT0 covers this group
            }
        }
    }
}

// ---------------- kernel 3a: per-row LSE terms, 32 CTAs --------------------
__global__ void reduce_rows_kernel() {
    __shared__ float s[8];
    int t = threadIdx.x;
    int row = blockIdx.x * 256 + t;            // RCTAS*256 = 8192 rows
    const float* p = g_part + (size_t)row * SLOTS;
    float sum2 = (p[0] + p[1]) + (p[2] + p[3]);
    float v = __logf(sum2) - g_diag[row];      // LSE - diag (natural units)
    #pragma unroll
    for (int o = 16; o; o >>= 1) v += __shfl_xor_sync(0xffffffffu, v, o);
    if ((t & 31) == 0) s[t >> 5] = v;
    __syncthreads();
    if (t < 32) {
        float x = (t < 8) ? s[t] : 0.f;
        #pragma unroll
        for (int o = 4; o; o >>= 1) x += __shfl_xor_sync(0xffffffffu, x, o);
        if (t == 0) g_bsum[blockIdx.x] = x;
    }
}

// ---------------- kernel 3b: final sum ------------------------------------
__global__ void reduce_final_kernel(float* __restrict__ out, int N) {
    int t = threadIdx.x;
    float x = (t < RCTAS) ? g_bsum[t] : 0.f;
    #pragma unroll
    for (int o = 16; o; o >>= 1) x += __shfl_xor_sync(0xffffffffu, x, o);
    if (t == 0) out[0] = x / (float)N;
}

// ---------------- launch ---------------------------------------------------
extern "C" void kernel_launch(void* const* d_in, const int* in_sizes, int n_in,
                              void* d_out, int out_size) {
    const float* a = (const float*)d_in[0];
    const float* b = (const float*)d_in[1];
    int N = in_sizes[0] / D;   // 8192

    cudaFuncSetAttribute(sim_lse_kernel,
                         cudaFuncAttributeMaxDynamicSharedMemorySize, SM_TOTAL);

    norm_kernel<<<N / 8, 256>>>((const float4*)a, (const float4*)b);
    sim_lse_kernel<<<GRIDZ, 256, SM_TOTAL>>>();
    reduce_rows_kernel<<<RCTAS, 256>>>();
    reduce_final_kernel<<<1, 32>>>((float*)d_out, N);
}

// round 15
// speedup vs baseline: 1.0627x; 1.0265x over previous
#include <cuda_runtime.h>
#include <cuda_bf16.h>
#include <cstdint>

#define D      256
#define MAXN   8192
#define BM     128                 // rows per row-block
#define BN     128                 // cols per tile
#define CTPB   64                  // col-tiles per row-block (MAXN/BN)
#define NTOT   4096                // total tiles = 64 rb x 64 ct
#define GRIDZ  148                 // one CTA per SM
#define SLOTS  4                   // max CTAs sharing one row-block
#define RCTAS  32                  // reduce stage-A CTAs
#define TILEB  65536               // bytes per 128x256 bf16 tile image
#define LOG2E_OVER_T 28.853900817779268f
#define INV_T        20.0f

// SMEM layout (bytes)
#define SM_PART 0                  // 2 x 128 floats = 1024
#define SM_MBAR 1024               // two 8B mbarriers
#define SM_A    2048               // 64KB swizzled A tile
#define SM_B0   (SM_A + TILEB)
#define SM_TOTAL (SM_B0 + 2 * TILEB)   // 198656

// ---------------- scratch: tile-major, PRE-SWIZZLED images -----------------
__device__ __align__(128) uint8_t g_at[CTPB * TILEB];   // A tiles (4MB)
__device__ __align__(128) uint8_t g_bt[CTPB * TILEB];   // B tiles (4MB)
__device__ float g_diag[MAXN];
__device__ float g_part[MAXN * SLOTS];
__device__ float g_bsum[RCTAS];

// ---------------- helpers --------------------------------------------------
__device__ __forceinline__ uint32_t smem_u32(const void* p) {
    return (uint32_t)__cvta_generic_to_shared(p);
}
__device__ __forceinline__ float ex2f(float x) {
    float y; asm("ex2.approx.f32 %0, %1;" : "=f"(y) : "f"(x)); return y;
}
__device__ __forceinline__ void ldsm_x4(uint32_t r[4], uint32_t addr) {
    asm volatile("ldmatrix.sync.aligned.m8n8.x4.shared.b16 {%0,%1,%2,%3}, [%4];"
                 : "=r"(r[0]), "=r"(r[1]), "=r"(r[2]), "=r"(r[3]) : "r"(addr));
}
__device__ __forceinline__ void mma_bf16(float c[4], const uint32_t a[4],
                                         uint32_t b0, uint32_t b1) {
    asm volatile(
        "mma.sync.aligned.m16n8k16.row.col.f32.bf16.bf16.f32 "
        "{%0,%1,%2,%3}, {%4,%5,%6,%7}, {%8,%9}, {%0,%1,%2,%3};\n"
        : "+f"(c[0]), "+f"(c[1]), "+f"(c[2]), "+f"(c[3])
        : "r"(a[0]), "r"(a[1]), "r"(a[2]), "r"(a[3]), "r"(b0), "r"(b1));
}
// ---- bulk async copy + mbarrier (sm_90 baseline PTX) ----
__device__ __forceinline__ void mbar_init(uint32_t mbar, uint32_t cnt) {
    asm volatile("mbarrier.init.shared.b64 [%0], %1;" :: "r"(mbar), "r"(cnt) : "memory");
}
__device__ __forceinline__ void mbar_arrive_expect_tx(uint32_t mbar, uint32_t bytes) {
    asm volatile("mbarrier.arrive.expect_tx.shared.b64 _, [%0], %1;"
                 :: "r"(mbar), "r"(bytes) : "memory");
}
__device__ __forceinline__ void bulk_g2s(uint32_t sdst, const void* gsrc,
                                         uint32_t bytes, uint32_t mbar) {
    asm volatile(
        "cp.async.bulk.shared::cta.global.mbarrier::complete_tx::bytes [%0], [%1], %2, [%3];"
        :: "r"(sdst), "l"(gsrc), "r"(bytes), "r"(mbar) : "memory");
}
__device__ __forceinline__ void mbar_wait(uint32_t mbar, uint32_t parity) {
    uint32_t done;
    asm volatile(
        "{\n\t.reg .pred p;\n\t"
        "mbarrier.try_wait.parity.acquire.cta.shared::cta.b64 p, [%1], %2;\n\t"
        "selp.b32 %0, 1, 0, p;\n\t}" : "=r"(done) : "r"(mbar), "r"(parity) : "memory");
    if (!done) {
        asm volatile(
            "{\n\t.reg .pred P1;\n\t"
            "WAIT_LOOP_%=:\n\t"
            "mbarrier.try_wait.parity.acquire.cta.shared::cta.b64 P1, [%0], %1, 0x989680;\n\t"
            "@P1 bra.uni WAIT_DONE_%=;\n\tbra.uni WAIT_LOOP_%=;\n\t"
            "WAIT_DONE_%=:\n\t}" :: "r"(mbar), "r"(parity) : "memory");
    }
}

// ---------------- kernel 1: norm + exact diag, PRE-SWIZZLED tile output ----
__global__ void norm_kernel(const float4* __restrict__ a4, const float4* __restrict__ b4) {
    // zero the partial-sum slots (grid 1024 x 256 covers 32768 floats)
    int gt = blockIdx.x * 256 + threadIdx.x;
    if (gt < MAXN * SLOTS) g_part[gt] = 0.f;

    int w = threadIdx.x >> 5, lane = threadIdx.x & 31;
    int row = blockIdx.x * 8 + w;
    const float4* ar = a4 + (size_t)row * (D / 4);
    const float4* br = b4 + (size_t)row * (D / 4);
    float4 a0 = ar[lane * 2], a1 = ar[lane * 2 + 1];
    float4 b0 = br[lane * 2], b1 = br[lane * 2 + 1];

    float sa = a0.x*a0.x + a0.y*a0.y + a0.z*a0.z + a0.w*a0.w
             + a1.x*a1.x + a1.y*a1.y + a1.z*a1.z + a1.w*a1.w;
    float sb = b0.x*b0.x + b0.y*b0.y + b0.z*b0.z + b0.w*b0.w
             + b1.x*b1.x + b1.y*b1.y + b1.z*b1.z + b1.w*b1.w;
    float sd = a0.x*b0.x + a0.y*b0.y + a0.z*b0.z + a0.w*b0.w
             + a1.x*b1.x + a1.y*b1.y + a1.z*b1.z + a1.w*b1.w;
    #pragma unroll
    for (int o = 16; o; o >>= 1) {
        sa += __shfl_xor_sync(0xffffffffu, sa, o);
        sb += __shfl_xor_sync(0xffffffffu, sb, o);
        sd += __shfl_xor_sync(0xffffffffu, sd, o);
    }
    float ia = rsqrtf(fmaxf(sa, 1e-16f));
    float ib = rsqrtf(fmaxf(sb, 1e-16f));
    if (lane == 0) g_diag[row] = sd * ia * ib * INV_T;

    // destination: tile-major image, byte-identical to the smem tile layout
    // offset = tile*TILEB + rt*512 + ((chunk ^ (rt&7)) << 4), chunk = lane
    int rt = row & 127;
    size_t dst_off = (size_t)(row >> 7) * TILEB + rt * 512
                   + (uint32_t)((lane ^ (rt & 7)) << 4);

    float fa = ia * LOG2E_OVER_T;
    __nv_bfloat162 p0 = __floats2bfloat162_rn(a0.x*fa, a0.y*fa);
    __nv_bfloat162 p1 = __floats2bfloat162_rn(a0.z*fa, a0.w*fa);
    __nv_bfloat162 p2 = __floats2bfloat162_rn(a1.x*fa, a1.y*fa);
    __nv_bfloat162 p3 = __floats2bfloat162_rn(a1.z*fa, a1.w*fa);
    uint4 ua = { *(uint32_t*)&p0, *(uint32_t*)&p1, *(uint32_t*)&p2, *(uint32_t*)&p3 };
    *(uint4*)(g_at + dst_off) = ua;

    __nv_bfloat162 q0 = __floats2bfloat162_rn(b0.x*ib, b0.y*ib);
    __nv_bfloat162 q1 = __floats2bfloat162_rn(b0.z*ib, b0.w*ib);
    __nv_bfloat162 q2 = __floats2bfloat162_rn(b1.x*ib, b1.y*ib);
    __nv_bfloat162 q3 = __floats2bfloat162_rn(b1.z*ib, b1.w*ib);
    uint4 ub = { *(uint32_t*)&q0, *(uint32_t*)&q1, *(uint32_t*)&q2, *(uint32_t*)&q3 };
    *(uint4*)(g_bt + dst_off) = ub;
}

// ---------------- kernel 2: HMMA GEMM + ex2, bulk-copy pipeline ------------
__global__ __launch_bounds__(256, 1) void sim_lse_kernel() {
    extern __shared__ char sm[];
    uint32_t sbase = smem_u32(sm);
    int tid = threadIdx.x, w = tid >> 5, lane = tid & 31;
    int cta = blockIdx.x;
    int gStart = (cta * NTOT) / GRIDZ;
    int gEnd   = ((cta + 1) * NTOT) / GRIDZ;

    int wr = (w & 3) * 32;        // warp row offset
    int wc = (w >> 2) * 64;       // warp col offset
    int g2 = lane >> 3, l3 = lane & 7;
    uint32_t rk = (uint32_t)(l3 >> 1);

    uint32_t abase[2], boff[4];
    {
        uint32_t c0a = (uint32_t)(((g2 >> 1) ^ (l3 & 1)) << 4);
        uint32_t c0b = (uint32_t)(((g2 & 1) ^ (l3 & 1)) << 4);
        #pragma unroll
        for (int mt = 0; mt < 2; mt++) {
            int row = wr + mt * 16 + (g2 & 1) * 8 + l3;
            abase[mt] = sbase + SM_A + row * 512 + c0a;
        }
        #pragma unroll
        for (int nt = 0; nt < 4; nt++) {
            int n = wc + nt * 16 + (g2 >> 1) * 8 + l3;
            boff[nt] = (uint32_t)(n * 512) + c0b;
        }
    }

    uint32_t mbar[2] = { sbase + SM_MBAR, sbase + SM_MBAR + 8 };
    int ph[2] = { 0, 0 };
    if (tid == 0) { mbar_init(mbar[0], 1); mbar_init(mbar[1], 1); }
    __syncthreads();

    int rb = gStart >> 6;
    if (tid == 0) {   // prologue: A(rb) + B(gStart) on buffer gStart&1
        int b = gStart & 1;
        mbar_arrive_expect_tx(mbar[b], 2 * TILEB);
        bulk_g2s(sbase + SM_A, g_at + (size_t)rb * TILEB, TILEB, mbar[b]);
        bulk_g2s(sbase + SM_B0 + b * TILEB,
                 g_bt + (size_t)(gStart & (CTPB - 1)) * TILEB, TILEB, mbar[b]);
    }

    float acc[2][8][4];
    #pragma unroll
    for (int mt = 0; mt < 2; mt++)
        #pragma unroll
        for (int j = 0; j < 8; j++)
            acc[mt][j][0] = acc[mt][j][1] = acc[mt][j][2] = acc[mt][j][3] = 0.f;
    float rs0[2] = {0, 0}, rs1[2] = {0, 0};
    float* partial = (float*)(sm + SM_PART);

    for (int g = gStart; g < gEnd; g++) {
        int buf = g & 1;
        mbar_wait(mbar[buf], ph[buf]);   // tile g (and bundled A) arrived
        ph[buf] ^= 1;
        __syncthreads();                 // all warps past iter g-1's k-loop:
                                         // buffer buf^1 is reusable
        bool boundary = ((g + 1) & (CTPB - 1)) == 0;
        if (g + 1 < gEnd && !boundary && tid == 0) {
            mbar_arrive_expect_tx(mbar[buf ^ 1], TILEB);
            bulk_g2s(sbase + SM_B0 + (buf ^ 1) * TILEB,
                     g_bt + (size_t)((g + 1) & (CTPB - 1)) * TILEB,
                     TILEB, mbar[buf ^ 1]);
        }

        uint32_t bbuf = sbase + SM_B0 + buf * TILEB;

        #pragma unroll
        for (int kk = 0; kk < 16; kk++) {
            uint32_t koff = ((uint32_t)(kk ^ rk)) << 5;
            uint32_t af[2][4], bf[4][4];
            #pragma unroll
            for (int mt = 0; mt < 2; mt++) ldsm_x4(af[mt], abase[mt] + koff);
            #pragma unroll
            for (int nt = 0; nt < 4; nt++) ldsm_x4(bf[nt], bbuf + boff[nt] + koff);
            #pragma unroll
            for (int mt = 0; mt < 2; mt++) {
                #pragma unroll
                for (int nt = 0; nt < 4; nt++) {
                    mma_bf16(acc[mt][nt * 2],     af[mt], bf[nt][0], bf[nt][1]);
                    mma_bf16(acc[mt][nt * 2 + 1], af[mt], bf[nt][2], bf[nt][3]);
                }
            }
        }
        #pragma unroll
        for (int mt = 0; mt < 2; mt++)
            #pragma unroll
            for (int j = 0; j < 8; j++) {
                rs0[mt] += ex2f(acc[mt][j][0]) + ex2f(acc[mt][j][1]);
                rs1[mt] += ex2f(acc[mt][j][2]) + ex2f(acc[mt][j][3]);
                acc[mt][j][0] = acc[mt][j][1] = acc[mt][j][2] = acc[mt][j][3] = 0.f;
            }

        if (boundary || g + 1 == gEnd) {
            #pragma unroll
            for (int mt = 0; mt < 2; mt++) {
                rs0[mt] += __shfl_xor_sync(0xffffffffu, rs0[mt], 1);
                rs0[mt] += __shfl_xor_sync(0xffffffffu, rs0[mt], 2);
                rs1[mt] += __shfl_xor_sync(0xffffffffu, rs1[mt], 1);
                rs1[mt] += __shfl_xor_sync(0xffffffffu, rs1[mt], 2);
            }
            if ((lane & 3) == 0) {
                int half = (w >> 2) * 128;
                #pragma unroll
                for (int mt = 0; mt < 2; mt++) {
                    partial[half + wr + mt * 16 + (lane >> 2)]     = rs0[mt];
                    partial[half + wr + mt * 16 + 8 + (lane >> 2)] = rs1[mt];
                }
            }
            __syncthreads();   // partials visible; all warps out of k-loop (A free)
            int ft = rb << 6;
            int i0 = (ft * GRIDZ) / NTOT;
            while (((i0 + 1) * NTOT) / GRIDZ <= ft) i0++;
            int slot = cta - i0;   // 0..SLOTS-1
            if (tid < 128)
                g_part[(size_t)(rb * BM + tid) * SLOTS + slot] =
                    partial[tid] + partial[128 + tid];
            rs0[0] = rs0[1] = rs1[0] = rs1[1] = 0.f;
            if (boundary && g + 1 < gEnd) {
                rb = (g + 1) >> 6;
                if (tid == 0) {    // bundle next A + next B on one barrier
                    int nb = buf ^ 1;
                    mbar_arrive_expect_tx(mbar[nb], 2 * TILEB);
                    bulk_g2s(sbase + SM_A, g_at + (size_t)rb * TILEB,
                             TILEB, mbar[nb]);
                    bulk_g2s(sbase + SM_B0 + nb * TILEB,
                             g_bt + (size_t)((g + 1) & (CTPB - 1)) * TILEB,
                             TILEB, mbar[nb]);
                }
            }
        }
    }
}

// ---------------- kernel 3a: per-row LSE terms, 32 CTAs --------------------
__global__ void reduce_rows_kernel() {
    __shared__ float s[8];
    int t = threadIdx.x;
    int row = blockIdx.x * 256 + t;            // RCTAS*256 = 8192 rows
    const float* p = g_part + (size_t)row * SLOTS;
    float sum2 = (p[0] + p[1]) + (p[2] + p[3]);
    float v = __logf(sum2) - g_diag[row];      // LSE - diag (natural units)
    #pragma unroll
    for (int o = 16; o; o >>= 1) v += __shfl_xor_sync(0xffffffffu, v, o);
    if ((t & 31) == 0) s[t >> 5] = v;
    __syncthreads();
    if (t < 32) {
        float x = (t < 8) ? s[t] : 0.f;
        #pragma unroll
        for (int o = 4; o; o >>= 1) x += __shfl_xor_sync(0xffffffffu, x, o);
        if (t == 0) g_bsum[blockIdx.x] = x;
    }
}

// ---------------- kernel 3b: final sum ------------------------------------
__global__ void reduce_final_kernel(float* __restrict__ out, int N) {
    int t = threadIdx.x;
    float x = (t < RCTAS) ? g_bsum[t] : 0.f;
    #pragma unroll
    for (int o = 16; o; o >>= 1) x += __shfl_xor_sync(0xffffffffu, x, o);
    if (t == 0) out[0] = x / (float)N;
}

// ---------------- launch ---------------------------------------------------
extern "C" void kernel_launch(void* const* d_in, const int* in_sizes, int n_in,
                              void* d_out, int out_size) {
    const float* a = (const float*)d_in[0];
    const float* b = (const float*)d_in[1];
    int N = in_sizes[0] / D;   // 8192

    cudaFuncSetAttribute(sim_lse_kernel,
                         cudaFuncAttributeMaxDynamicSharedMemorySize, SM_TOTAL);

    norm_kernel<<<N / 8, 256>>>((const float4*)a, (const float4*)b);
    sim_lse_kernel<<<GRIDZ, 256, SM_TOTAL>>>();
    reduce_rows_kernel<<<RCTAS, 256>>>();
    reduce_final_kernel<<<1, 32>>>((float*)d_out, N);
}